// round 14
// baseline (speedup 1.0000x reference)
#include <cuda_runtime.h>

#define N_STATE 131072
#define H 128
#define SEG 64          // n-segments in kernel A
#define RPB 4           // rows per block in kernel A
#define JSPLIT 16       // i-splits in kernel C
#define JROWS (H / JSPLIT)

// Scratch (device globals — no allocation allowed)
__device__ float g_xnorm[N_STATE];
__device__ float g_scale[N_STATE];
__device__ float g_ypart[SEG * H];
__device__ float g_r[H];
__device__ float g_jvpart[JSPLIT * N_STATE];

// 32-byte W0 load with L2 evict_last hint (sm_100 requires v4.b64 width for
// this modifier). W0 (64MB) is re-read every graph replay in both passes;
// tagging it evict_last keeps it L2-resident across replays (L2 is not
// flushed between graph launches; only L1 is).
__device__ __forceinline__ void ldg_el8(const float* __restrict__ p,
                                        float4& a, float4& b)
{
    unsigned long long u0, u1, u2, u3;
    asm volatile("ld.global.nc.L2::evict_last.v4.b64 {%0,%1,%2,%3}, [%4];"
                 : "=l"(u0), "=l"(u1), "=l"(u2), "=l"(u3)
                 : "l"(p));
    a.x = __uint_as_float((unsigned)u0);  a.y = __uint_as_float((unsigned)(u0 >> 32));
    a.z = __uint_as_float((unsigned)u1);  a.w = __uint_as_float((unsigned)(u1 >> 32));
    b.x = __uint_as_float((unsigned)u2);  b.y = __uint_as_float((unsigned)(u2 >> 32));
    b.z = __uint_as_float((unsigned)u3);  b.w = __uint_as_float((unsigned)(u3 >> 32));
}

// ---------------------------------------------------------------------------
// Kernel N: x_norm[n] = (2 s - mx - mn) / (mx - mn);  scale[n] = 2/(mx - mn)
// ---------------------------------------------------------------------------
__global__ __launch_bounds__(256)
void k_norm(const float* __restrict__ state,
            const float* __restrict__ xmax,
            const float* __restrict__ xmin)
{
    const int i = blockIdx.x * blockDim.x + threadIdx.x;   // float4 index
    float4 s  = ((const float4*)state)[i];
    float4 mx = ((const float4*)xmax)[i];
    float4 mn = ((const float4*)xmin)[i];
    float4 inv, xn, sc;
    inv.x = 1.0f / (mx.x - mn.x);
    inv.y = 1.0f / (mx.y - mn.y);
    inv.z = 1.0f / (mx.z - mn.z);
    inv.w = 1.0f / (mx.w - mn.w);
    xn.x = (2.0f * s.x - mx.x - mn.x) * inv.x;
    xn.y = (2.0f * s.y - mx.y - mn.y) * inv.y;
    xn.z = (2.0f * s.z - mx.z - mn.z) * inv.z;
    xn.w = (2.0f * s.w - mx.w - mn.w) * inv.w;
    sc.x = 2.0f * inv.x;  sc.y = 2.0f * inv.y;
    sc.z = 2.0f * inv.z;  sc.w = 2.0f * inv.w;
    ((float4*)g_xnorm)[i] = xn;
    ((float4*)g_scale)[i] = sc;
}

// ---------------------------------------------------------------------------
// Kernel A: partial y. grid (SEG=64, 32 rowgroups) = 2048 blocks x 256 thr.
// Each thread owns one float8 column-slab; RPB=4 rows, one 32B evict_last
// load per row.
// ---------------------------------------------------------------------------
__global__ __launch_bounds__(256)
void k_fwd_matvec(const float* __restrict__ W0)
{
    const int seg = blockIdx.x;
    const int row0 = blockIdx.y * RPB;
    const int chunk = N_STATE / SEG;                       // 2048 floats
    const int col = seg * chunk + threadIdx.x * 8;         // this thread's 8 cols

    // x chunk (regular loads)
    float4 x0 = *(const float4*)(g_xnorm + col);
    float4 x1 = *(const float4*)(g_xnorm + col + 4);

    float acc[RPB];
    #pragma unroll
    for (int r = 0; r < RPB; r++) {
        float4 a, b;
        ldg_el8(W0 + (size_t)(row0 + r) * N_STATE + col, a, b);
        acc[r] = a.x * x0.x + a.y * x0.y + a.z * x0.z + a.w * x0.w
               + b.x * x1.x + b.y * x1.y + b.z * x1.z + b.w * x1.w;
    }

    __shared__ float red[8][RPB];
    const int lane = threadIdx.x & 31, warp = threadIdx.x >> 5;
    #pragma unroll
    for (int r = 0; r < RPB; r++) {
        float v = acc[r];
        #pragma unroll
        for (int o = 16; o > 0; o >>= 1)
            v += __shfl_down_sync(0xffffffffu, v, o);
        if (lane == 0) red[warp][r] = v;
    }
    __syncthreads();
    if (threadIdx.x < RPB) {
        float v = 0.0f;
        #pragma unroll
        for (int w = 0; w < 8; w++) v += red[w][threadIdx.x];
        g_ypart[seg * H + row0 + threadIdx.x] = v;
    }
}

// ---------------------------------------------------------------------------
// Kernel B: core, 128 threads. Warp-cooperative forward matvecs (coalesced
// row loads + shfl reduce); coalesced column walks for the backward collapse.
// ---------------------------------------------------------------------------
__global__ __launch_bounds__(128, 1)
void k_core(const float* __restrict__ b0,
            const float* __restrict__ W1, const float* __restrict__ b1,
            const float* __restrict__ W2, const float* __restrict__ b2,
            const float* __restrict__ W3, const float* __restrict__ b3,
            const float* __restrict__ Wout, const float* __restrict__ bout,
            float* __restrict__ out)
{
    __shared__ float v[H];
    __shared__ float tv[H];
    __shared__ float d0[H], d1[H], d2[H];

    const int tid = threadIdx.x;
    const int lane = tid & 31, warp = tid >> 5;

    float y = 0.0f;
    #pragma unroll
    for (int s = 0; s < SEG; s++) y += g_ypart[s * H + tid];

    float V = tanhf(y + b0[tid]);
    d0[tid] = 1.0f - V * V;
    v[tid] = V;
    __syncthreads();

    #define FWD_MATVEC(Wm, vn)                                                 \
    {                                                                          \
        float4 vv = ((const float4*)v)[lane];                                  \
        _Pragma("unroll")                                                      \
        for (int jj = 0; jj < 32; jj++) {                                      \
            const int j = warp * 32 + jj;                                      \
            float4 wv = ((const float4*)(Wm + j * H))[lane];                   \
            float p = wv.x * vv.x + wv.y * vv.y + wv.z * vv.z + wv.w * vv.w;   \
            _Pragma("unroll")                                                  \
            for (int o = 16; o > 0; o >>= 1)                                   \
                p += __shfl_xor_sync(0xffffffffu, p, o);                       \
            if (lane == jj) vn = p;                                            \
        }                                                                      \
    }

    float vn = 0.0f;
    FWD_MATVEC(W1, vn);
    V = tanhf(vn + b1[tid]);
    d1[tid] = 1.0f - V * V;
    __syncthreads();
    v[tid] = V;
    __syncthreads();

    FWD_MATVEC(W2, vn);
    V = tanhf(vn + b2[tid]);
    d2[tid] = 1.0f - V * V;
    __syncthreads();
    v[tid] = V;
    __syncthreads();

    FWD_MATVEC(W3, vn);
    V = vn + b3[tid];
    __syncthreads();
    v[tid] = V;
    __syncthreads();

    if (tid < 32) {
        float p = 0.0f;
        #pragma unroll
        for (int s = 0; s < 4; s++)
            p += Wout[tid + 32 * s] * v[tid + 32 * s];
        #pragma unroll
        for (int o = 16; o > 0; o >>= 1)
            p += __shfl_down_sync(0xffffffffu, p, o);
        if (tid == 0) out[0] = p + bout[0];
    }

    // backward: r^T = Wout W3 D2 W2 D1 W1 D0
    tv[tid] = Wout[tid];
    __syncthreads();

    {
        float a = 0.0f;
        #pragma unroll 16
        for (int i = 0; i < H; i++) a += tv[i] * W3[i * H + tid];
        a *= d2[tid];
        __syncthreads();
        tv[tid] = a;
        __syncthreads();
    }
    {
        float a = 0.0f;
        #pragma unroll 16
        for (int i = 0; i < H; i++) a += tv[i] * W2[i * H + tid];
        a *= d1[tid];
        __syncthreads();
        tv[tid] = a;
        __syncthreads();
    }
    {
        float a = 0.0f;
        #pragma unroll 16
        for (int i = 0; i < H; i++) a += tv[i] * W1[i * H + tid];
        g_r[tid] = a * d0[tid];
    }
    #undef FWD_MATVEC
}

// ---------------------------------------------------------------------------
// Kernel C: partial JV with 32B evict_last loads. blockIdx.x = n-chunk
// (float8), blockIdx.y = i-split. grid (64, 16) = 1024 blocks x 256 thr,
// JROWS=8 rows per thread, fully unrolled.
// ---------------------------------------------------------------------------
__global__ __launch_bounds__(256)
void k_jv_part(const float* __restrict__ W0)
{
    __shared__ float r[JROWS];
    const int i0 = blockIdx.y * JROWS;
    if (threadIdx.x < JROWS) r[threadIdx.x] = g_r[i0 + threadIdx.x];
    __syncthreads();

    const int n = (blockIdx.x * blockDim.x + threadIdx.x) * 8;  // first of 8 cols

    float4 accA = make_float4(0.f, 0.f, 0.f, 0.f);
    float4 accB = make_float4(0.f, 0.f, 0.f, 0.f);
    #pragma unroll
    for (int i = 0; i < JROWS; i++) {                      // 8 rows
        float4 a, b;
        ldg_el8(W0 + (size_t)(i0 + i) * N_STATE + n, a, b);
        float ri = r[i];
        accA.x += ri * a.x;  accA.y += ri * a.y;
        accA.z += ri * a.z;  accA.w += ri * a.w;
        accB.x += ri * b.x;  accB.y += ri * b.y;
        accB.z += ri * b.z;  accB.w += ri * b.w;
    }

    float* dst = g_jvpart + (size_t)blockIdx.y * N_STATE + n;
    *(float4*)dst       = accA;
    *(float4*)(dst + 4) = accB;
}

// ---------------------------------------------------------------------------
// Kernel D: combine 16 partials, apply scale, write out[1..N].
// ---------------------------------------------------------------------------
__global__ __launch_bounds__(256)
void k_combine(float* __restrict__ out)
{
    const int i4 = blockIdx.x * blockDim.x + threadIdx.x;   // float4 index
    float ax = 0.0f, ay = 0.0f, az = 0.0f, aw = 0.0f;
    #pragma unroll
    for (int s = 0; s < JSPLIT; s++) {
        float4 p = ((const float4*)(g_jvpart + (size_t)s * N_STATE))[i4];
        ax += p.x; ay += p.y; az += p.z; aw += p.w;
    }
    float4 sc = ((const float4*)g_scale)[i4];
    const int n = i4 * 4;
    out[1 + n + 0] = ax * sc.x;
    out[1 + n + 1] = ay * sc.y;
    out[1 + n + 2] = az * sc.z;
    out[1 + n + 3] = aw * sc.w;
}

// ---------------------------------------------------------------------------
extern "C" void kernel_launch(void* const* d_in, const int* in_sizes, int n_in,
                              void* d_out, int out_size)
{
    const float* state = (const float*)d_in[0];
    const float* xmax  = (const float*)d_in[1];
    const float* xmin  = (const float*)d_in[2];
    const float* W0    = (const float*)d_in[3];
    const float* b0    = (const float*)d_in[4];
    const float* W1    = (const float*)d_in[5];
    const float* b1    = (const float*)d_in[6];
    const float* W2    = (const float*)d_in[7];
    const float* b2    = (const float*)d_in[8];
    const float* W3    = (const float*)d_in[9];
    const float* b3    = (const float*)d_in[10];
    const float* Wout  = (const float*)d_in[11];
    const float* bout  = (const float*)d_in[12];
    float* out = (float*)d_out;

    k_norm<<<N_STATE / 4 / 256, 256>>>(state, xmax, xmin);
    dim3 gridA(SEG, H / RPB);
    k_fwd_matvec<<<gridA, 256>>>(W0);
    k_core<<<1, H>>>(b0, W1, b1, W2, b2, W3, b3, Wout, bout, out);
    dim3 gridC(N_STATE / 8 / 256, JSPLIT);
    k_jv_part<<<gridC, 256>>>(W0);
    k_combine<<<N_STATE / 4 / 256, 256>>>(out);
}

// round 17
// speedup vs baseline: 1.1216x; 1.1216x over previous
#include <cuda_runtime.h>

#define N_STATE 131072
#define H 128
#define SEG 64          // n-segments in kernel A
#define RPB 4           // rows per block in kernel A

// Scratch (device globals — no allocation allowed)
__device__ float g_xnorm[N_STATE];
__device__ float g_scale[N_STATE];
__device__ float g_ypart[SEG * H];
__device__ float g_r[H];

// ---------------------------------------------------------------------------
// Kernel N: x_norm[n] = (2 s - mx - mn) / (mx - mn);  scale[n] = 2/(mx - mn)
// ---------------------------------------------------------------------------
__global__ __launch_bounds__(256)
void k_norm(const float* __restrict__ state,
            const float* __restrict__ xmax,
            const float* __restrict__ xmin)
{
    const int i = blockIdx.x * blockDim.x + threadIdx.x;   // float4 index
    float4 s  = ((const float4*)state)[i];
    float4 mx = ((const float4*)xmax)[i];
    float4 mn = ((const float4*)xmin)[i];
    float4 inv, xn, sc;
    inv.x = 1.0f / (mx.x - mn.x);
    inv.y = 1.0f / (mx.y - mn.y);
    inv.z = 1.0f / (mx.z - mn.z);
    inv.w = 1.0f / (mx.w - mn.w);
    xn.x = (2.0f * s.x - mx.x - mn.x) * inv.x;
    xn.y = (2.0f * s.y - mx.y - mn.y) * inv.y;
    xn.z = (2.0f * s.z - mx.z - mn.z) * inv.z;
    xn.w = (2.0f * s.w - mx.w - mn.w) * inv.w;
    sc.x = 2.0f * inv.x;  sc.y = 2.0f * inv.y;
    sc.z = 2.0f * inv.z;  sc.w = 2.0f * inv.w;
    ((float4*)g_xnorm)[i] = xn;
    ((float4*)g_scale)[i] = sc;
}

// ---------------------------------------------------------------------------
// Kernel A: partial y. grid (SEG=64, 32 rowgroups) = 2048 blocks x 256 thr.
// ---------------------------------------------------------------------------
__global__ __launch_bounds__(256)
void k_fwd_matvec(const float* __restrict__ W0)
{
    const int seg = blockIdx.x;
    const int row0 = blockIdx.y * RPB;
    const int chunk4 = (N_STATE / SEG) / 4;                // 512 float4s

    const float4* __restrict__ xn = (const float4*)g_xnorm + (size_t)seg * chunk4;
    const float4* __restrict__ w0 = (const float4*)(W0 + (size_t)row0 * N_STATE) + (size_t)seg * chunk4;
    const size_t rstride4 = N_STATE / 4;

    float acc[RPB];
    #pragma unroll
    for (int r = 0; r < RPB; r++) acc[r] = 0.0f;

    #pragma unroll
    for (int it = 0; it < (N_STATE / SEG) / 4 / 256; it++) {   // 2 its
        const int i = it * 256 + threadIdx.x;
        float4 x = xn[i];
        #pragma unroll
        for (int r = 0; r < RPB; r++) {
            float4 wv = w0[(size_t)r * rstride4 + i];
            acc[r] += wv.x * x.x + wv.y * x.y + wv.z * x.z + wv.w * x.w;
        }
    }

    __shared__ float red[8][RPB];
    const int lane = threadIdx.x & 31, warp = threadIdx.x >> 5;
    #pragma unroll
    for (int r = 0; r < RPB; r++) {
        float v = acc[r];
        #pragma unroll
        for (int o = 16; o > 0; o >>= 1)
            v += __shfl_down_sync(0xffffffffu, v, o);
        if (lane == 0) red[warp][r] = v;
    }
    __syncthreads();
    if (threadIdx.x < RPB) {
        float v = 0.0f;
        #pragma unroll
        for (int w = 0; w < 8; w++) v += red[w][threadIdx.x];
        g_ypart[seg * H + row0 + threadIdx.x] = v;
    }
}

// ---------------------------------------------------------------------------
// Kernel B: core, 128 threads. Warp-cooperative forward matvecs (coalesced
// row loads + shfl reduce); coalesced column walks for the backward collapse.
// ---------------------------------------------------------------------------
__global__ __launch_bounds__(128, 1)
void k_core(const float* __restrict__ b0,
            const float* __restrict__ W1, const float* __restrict__ b1,
            const float* __restrict__ W2, const float* __restrict__ b2,
            const float* __restrict__ W3, const float* __restrict__ b3,
            const float* __restrict__ Wout, const float* __restrict__ bout,
            float* __restrict__ out)
{
    __shared__ float v[H];
    __shared__ float tv[H];
    __shared__ float d0[H], d1[H], d2[H];

    const int tid = threadIdx.x;
    const int lane = tid & 31, warp = tid >> 5;

    float y = 0.0f;
    #pragma unroll
    for (int s = 0; s < SEG; s++) y += g_ypart[s * H + tid];

    float V = tanhf(y + b0[tid]);
    d0[tid] = 1.0f - V * V;
    v[tid] = V;
    __syncthreads();

    #define FWD_MATVEC(Wm, vn)                                                 \
    {                                                                          \
        float4 vv = ((const float4*)v)[lane];                                  \
        _Pragma("unroll")                                                      \
        for (int jj = 0; jj < 32; jj++) {                                      \
            const int j = warp * 32 + jj;                                      \
            float4 wv = ((const float4*)(Wm + j * H))[lane];                   \
            float p = wv.x * vv.x + wv.y * vv.y + wv.z * vv.z + wv.w * vv.w;   \
            _Pragma("unroll")                                                  \
            for (int o = 16; o > 0; o >>= 1)                                   \
                p += __shfl_xor_sync(0xffffffffu, p, o);                       \
            if (lane == jj) vn = p;                                            \
        }                                                                      \
    }

    float vn = 0.0f;
    FWD_MATVEC(W1, vn);
    V = tanhf(vn + b1[tid]);
    d1[tid] = 1.0f - V * V;
    __syncthreads();
    v[tid] = V;
    __syncthreads();

    FWD_MATVEC(W2, vn);
    V = tanhf(vn + b2[tid]);
    d2[tid] = 1.0f - V * V;
    __syncthreads();
    v[tid] = V;
    __syncthreads();

    FWD_MATVEC(W3, vn);
    V = vn + b3[tid];
    __syncthreads();
    v[tid] = V;
    __syncthreads();

    if (tid < 32) {
        float p = 0.0f;
        #pragma unroll
        for (int s = 0; s < 4; s++)
            p += Wout[tid + 32 * s] * v[tid + 32 * s];
        #pragma unroll
        for (int o = 16; o > 0; o >>= 1)
            p += __shfl_down_sync(0xffffffffu, p, o);
        if (tid == 0) out[0] = p + bout[0];
    }

    // backward: r^T = Wout W3 D2 W2 D1 W1 D0
    tv[tid] = Wout[tid];
    __syncthreads();

    {
        float a = 0.0f;
        #pragma unroll 16
        for (int i = 0; i < H; i++) a += tv[i] * W3[i * H + tid];
        a *= d2[tid];
        __syncthreads();
        tv[tid] = a;
        __syncthreads();
    }
    {
        float a = 0.0f;
        #pragma unroll 16
        for (int i = 0; i < H; i++) a += tv[i] * W2[i * H + tid];
        a *= d1[tid];
        __syncthreads();
        tv[tid] = a;
        __syncthreads();
    }
    {
        float a = 0.0f;
        #pragma unroll 16
        for (int i = 0; i < H; i++) a += tv[i] * W1[i * H + tid];
        g_r[tid] = a * d0[tid];
    }
    #undef FWD_MATVEC
}

// ---------------------------------------------------------------------------
// Kernel C: JV[n] = scale[n] * sum_i r[i] * W0[i, n]
// 256 blocks x 256 threads, float2 per thread (measured-best single pass).
// ---------------------------------------------------------------------------
__global__ __launch_bounds__(256, 4)
void k_jv(const float* __restrict__ W0, float* __restrict__ out)
{
    __shared__ float r[H];
    if (threadIdx.x < H) r[threadIdx.x] = g_r[threadIdx.x];
    __syncthreads();

    const int n2 = blockIdx.x * blockDim.x + threadIdx.x;   // float2 index
    const float2* __restrict__ w = (const float2*)W0;
    const size_t stride2 = N_STATE / 2;

    float ax = 0.0f, ay = 0.0f;
    #pragma unroll 16
    for (int i = 0; i < H; i++) {
        float2 wv = w[(size_t)i * stride2 + n2];
        float ri = r[i];
        ax += ri * wv.x;
        ay += ri * wv.y;
    }

    float2 sc = ((const float2*)g_scale)[n2];
    const int n = n2 * 2;
    out[1 + n + 0] = ax * sc.x;
    out[1 + n + 1] = ay * sc.y;
}

// ---------------------------------------------------------------------------
extern "C" void kernel_launch(void* const* d_in, const int* in_sizes, int n_in,
                              void* d_out, int out_size)
{
    const float* state = (const float*)d_in[0];
    const float* xmax  = (const float*)d_in[1];
    const float* xmin  = (const float*)d_in[2];
    const float* W0    = (const float*)d_in[3];
    const float* b0    = (const float*)d_in[4];
    const float* W1    = (const float*)d_in[5];
    const float* b1    = (const float*)d_in[6];
    const float* W2    = (const float*)d_in[7];
    const float* b2    = (const float*)d_in[8];
    const float* W3    = (const float*)d_in[9];
    const float* b3    = (const float*)d_in[10];
    const float* Wout  = (const float*)d_in[11];
    const float* bout  = (const float*)d_in[12];
    float* out = (float*)d_out;

    k_norm<<<N_STATE / 4 / 256, 256>>>(state, xmax, xmin);
    dim3 gridA(SEG, H / RPB);
    k_fwd_matvec<<<gridA, 256>>>(W0);
    k_core<<<1, H>>>(b0, W1, b1, W2, b2, W3, b3, Wout, bout, out);
    k_jv<<<(N_STATE / 2) / 256, 256>>>(W0, out);
}